// round 2
// baseline (speedup 1.0000x reference)
#include <cuda_runtime.h>
#include <cuda_bf16.h>
#include <math.h>

// Fixed problem shapes
#define BB      16
#define HH      352
#define WW      1216
#define NN      (HH * WW)          // 428032
#define PP      100000
#define BN      (BB * NN)          // 6848512
#define TYPEIND 5
#define MAXD    40.0f

#define WPB     (NN / 32)          // 13376 selector words per batch
#define WORDS   (BB * WPB)         // 214016 words total
#define TILE_W  418                // words per scan tile (WPB = 32*418 exactly)
#define TPB     32                 // tiles per batch
#define NTILES  (BB * TPB)         // 512 tiles total

// Static scratch (no runtime allocation allowed)
__device__ int      d_inv[NN];            // inverse permutation
__device__ unsigned d_permbits[WORDS];    // selector bits in PERMUTED order
__device__ int      d_tileCnt[NTILES];    // per-tile selected counts
__device__ int      d_tileOff[NTILES];    // exclusive scan of counts
__device__ int      d_valid[BB];
__device__ int      d_offset[BB];
__device__ int      d_compact[BN];        // compacted global lind values
__device__ float    d_depthc[BN];         // depth at compacted positions

// ---------------------------------------------------------------------------
// K1: build inverse permutation; zero the bit array and tile counters.
// grid covers NN threads (NN > WORDS > NTILES).
// ---------------------------------------------------------------------------
__global__ void k_prep(const int* __restrict__ perm) {
    int gid = blockIdx.x * blockDim.x + threadIdx.x;
    if (gid < WORDS)  d_permbits[gid] = 0u;
    if (gid < NTILES) d_tileCnt[gid] = 0;
    if (gid < NN)     d_inv[perm[gid]] = gid;
}

// ---------------------------------------------------------------------------
// K2: stream selector over all pixels (vectorized x4). For the ~2.6% selected
// pixels: look up permuted position j and set bit j (+ count per tile).
// ---------------------------------------------------------------------------
__global__ void k_select(const int* __restrict__ label,
                         const float* __restrict__ depth) {
    int t   = blockIdx.x * blockDim.x + threadIdx.x;
    int gid = t * 4;                              // BN divisible by 4
    int4   lab = *reinterpret_cast<const int4*>(label + gid);
    float4 dep = *reinterpret_cast<const float4*>(depth + gid);

    int b       = gid / NN;                       // NN % 4 == 0: one batch per quad
    int pixBase = gid - b * NN;
    unsigned* pb = d_permbits + b * WPB;
    int*      tc = d_tileCnt + b * TPB;

    int labs[4]   = {lab.x, lab.y, lab.z, lab.w};
    float deps[4] = {dep.x, dep.y, dep.z, dep.w};
#pragma unroll
    for (int k = 0; k < 4; k++) {
        if (labs[k] == TYPEIND && deps[k] < MAXD) {
            int j = d_inv[pixBase + k];
            atomicOr(&pb[j >> 5], 1u << (j & 31));
            atomicAdd(&tc[(j >> 5) / TILE_W], 1);
        }
    }
}

// ---------------------------------------------------------------------------
// K3: single-block exclusive scan of the 512 tile counts + batch stats.
// ---------------------------------------------------------------------------
__global__ void k_scan() {
    __shared__ int s[NTILES];
    int t = threadIdx.x;
    int v = d_tileCnt[t];
    s[t] = v;
    __syncthreads();
    for (int off = 1; off < NTILES; off <<= 1) {
        int a = (t >= off) ? s[t - off] : 0;
        __syncthreads();
        s[t] += a;
        __syncthreads();
    }
    d_tileOff[t] = s[t] - v;                       // exclusive
    __syncthreads();
    if (t < BB) {
        int off_b = d_tileOff[t * TPB];
        int nxt   = (t == BB - 1) ? s[NTILES - 1] : d_tileOff[(t + 1) * TPB];
        d_offset[t] = off_b;
        d_valid[t]  = nxt - off_b;
    }
}

// ---------------------------------------------------------------------------
// K4: order-preserving compaction from the permuted bit array.
// grid = NTILES blocks x 128 threads; each tile = 418 words, 4 strips of 128.
// ---------------------------------------------------------------------------
__global__ void k_compact(const int* __restrict__ perm,
                          const float* __restrict__ depth) {
    int tile = blockIdx.x;
    int t    = threadIdx.x;
    int lane = t & 31, wid = t >> 5;
    __shared__ int warpS[4];

    int running = d_tileOff[tile];
    int b  = tile / TPB;                           // tiles aligned to batches
    int bn = b * NN;
    const int wbatch0 = (tile - b * TPB) * TILE_W; // first word-in-batch of tile

#pragma unroll
    for (int i = 0; i < 4; i++) {
        int widx = i * 128 + t;
        unsigned bits = 0;
        if (widx < TILE_W) bits = d_permbits[b * WPB + wbatch0 + widx];
        int c = __popc(bits);

        // block-wide exclusive scan of c (4 warps)
        int inc = c;
#pragma unroll
        for (int off = 1; off < 32; off <<= 1) {
            int n = __shfl_up_sync(0xffffffffu, inc, off);
            if (lane >= off) inc += n;
        }
        if (lane == 31) warpS[wid] = inc;
        __syncthreads();
        int wbase = 0;
#pragma unroll
        for (int w = 0; w < 4; w++) if (w < wid) wbase += warpS[w];
        int slot = running + wbase + inc - c;
        int tot  = warpS[0] + warpS[1] + warpS[2] + warpS[3];

        if (bits) {
            int jbase = (wbatch0 + widx) * 32;     // permuted index base
            while (bits) {
                int l = __ffs(bits) - 1;
                bits &= bits - 1;
                int pix = perm[jbase + l];
                int val = bn + pix;
                d_compact[slot] = val;
                d_depthc[slot]  = depth[val];
                slot++;
            }
        }
        running += tot;
        __syncthreads();                           // warpS reuse
    }
}

// ---------------------------------------------------------------------------
// K5: sample + back-project; write [B,3,P] points then [B] indicator.
// ---------------------------------------------------------------------------
__global__ void k_output(const float* __restrict__ invK,
                         const float* __restrict__ bind,
                         float* __restrict__ out) {
    int i = blockIdx.x * blockDim.x + threadIdx.x;
    if (i < BB)
        out[3 * BB * PP + i] = (d_valid[i] > 0) ? 1.0f : 0.0f;
    if (i >= BB * PP) return;

    int b = i / PP;
    int p = i - b * PP;
    int vn = d_valid[b];

    int idx = 0;
    if (vn > 0)
        idx = (int)fmodf(bind[i], (float)vn) + d_offset[b];

    int   pos = d_compact[idx];
    float d   = d_depthc[idx];
    int bb  = pos / NN;
    int pix = pos - bb * NN;
    int q   = pix / WW;
    float y = (float)q;
    float x = (float)(pix - q * WW);
    float hx = x * d, hy = y * d;

    const float* M = invK + bb * 16;
#pragma unroll
    for (int c = 0; c < 3; c++) {
        float v = fmaf(__ldg(&M[c * 4 + 0]), hx,
                  fmaf(__ldg(&M[c * 4 + 1]), hy,
                  fmaf(__ldg(&M[c * 4 + 2]), d, __ldg(&M[c * 4 + 3]))));
        out[(b * 3 + c) * PP + p] = v;
    }
}

// ---------------------------------------------------------------------------
extern "C" void kernel_launch(void* const* d_in, const int* in_sizes, int n_in,
                              void* d_out, int out_size) {
    const float* predDepth = (const float*)d_in[0];   // [B,1,H,W]
    const float* invcamK   = (const float*)d_in[1];   // [B,4,4]
    const int*   semLabel  = (const int*)  d_in[2];   // [B,1,H,W]
    const float* bind      = (const float*)d_in[3];   // [B,P]
    const int*   perm      = (const int*)  d_in[4];   // [N]
    float* out = (float*)d_out;

    k_prep   <<<NN / 256, 256>>>(perm);
    k_select <<<BN / 1024, 256>>>(semLabel, predDepth);
    k_scan   <<<1, NTILES>>>();
    k_compact<<<NTILES, 128>>>(perm, predDepth);
    k_output <<<(BB * PP) / 256, 256>>>(invcamK, bind, out);
}

// round 3
// speedup vs baseline: 2.1483x; 2.1483x over previous
#include <cuda_runtime.h>
#include <cuda_bf16.h>
#include <math.h>

// Fixed problem shapes
#define BB      16
#define HH      352
#define WW      1216
#define NN      (HH * WW)          // 428032
#define PP      100000
#define BN      (BB * NN)          // 6848512
#define TYPEIND 5
#define MAXD    40.0f

#define WPB     (NN / 32)          // 13376 selector words per batch
#define WORDS   (BB * WPB)         // 214016 words total
#define TPB     64                 // tiles per batch
#define TILE_W  (WPB / TPB)        // 209 words per tile (exact: 13376 = 64*209)
#define NTILES  (BB * TPB)         // 1024 tiles total

// Static scratch (no runtime allocation allowed)
__device__ int      d_inv[NN];            // inverse permutation
__device__ unsigned d_permbits[WORDS];    // selector bits in PERMUTED order
__device__ int      d_tileCnt[NTILES];
__device__ int      d_tileOff[NTILES];
__device__ int      d_valid[BB];
__device__ int      d_offset[BB];
__device__ int2     d_cd[BN];             // {global lind, depth bits} compacted

// ---------------------------------------------------------------------------
// K1: build inverse permutation; zero the bit array.
// ---------------------------------------------------------------------------
__global__ void k_prep(const int* __restrict__ perm) {
    int gid = blockIdx.x * blockDim.x + threadIdx.x;
    if (gid < WORDS) d_permbits[gid] = 0u;
    if (gid < NN)    d_inv[perm[gid]] = gid;
}

// ---------------------------------------------------------------------------
// K2: stream selector over all pixels (vectorized x4). Selected pixels
// (~2.6%) set their bit at permuted position j.
// ---------------------------------------------------------------------------
__global__ void k_select(const int* __restrict__ label,
                         const float* __restrict__ depth) {
    int t   = blockIdx.x * blockDim.x + threadIdx.x;
    int gid = t * 4;                              // BN divisible by 4
    int4   lab = *reinterpret_cast<const int4*>(label + gid);
    float4 dep = *reinterpret_cast<const float4*>(depth + gid);

    int b       = gid / NN;                       // NN % 4 == 0
    int pixBase = gid - b * NN;
    unsigned* pb = d_permbits + b * WPB;

    int labs[4]   = {lab.x, lab.y, lab.z, lab.w};
    float deps[4] = {dep.x, dep.y, dep.z, dep.w};
#pragma unroll
    for (int k = 0; k < 4; k++) {
        if (labs[k] == TYPEIND && deps[k] < MAXD) {
            int j = d_inv[pixBase + k];
            atomicOr(&pb[j >> 5], 1u << (j & 31));
        }
    }
}

// ---------------------------------------------------------------------------
// K3: per-tile popcount. grid = NTILES x 128 threads (209 words/tile).
// ---------------------------------------------------------------------------
__global__ void k_count() {
    int blk = blockIdx.x;
    int t   = threadIdx.x;
    const unsigned* w = d_permbits + blk * TILE_W;
    int c = 0;
    if (t < TILE_W)       c += __popc(w[t]);
    if (t + 128 < TILE_W) c += __popc(w[t + 128]);
#pragma unroll
    for (int off = 16; off; off >>= 1)
        c += __shfl_down_sync(0xffffffffu, c, off);
    __shared__ int ws[4];
    if ((t & 31) == 0) ws[t >> 5] = c;
    __syncthreads();
    if (t == 0) d_tileCnt[blk] = ws[0] + ws[1] + ws[2] + ws[3];
}

// ---------------------------------------------------------------------------
// K4: single-block exclusive scan of 1024 tile counts + batch stats.
// ---------------------------------------------------------------------------
__global__ void k_scan() {
    __shared__ int s[NTILES];
    int t = threadIdx.x;
    int v = d_tileCnt[t];
    s[t] = v;
    __syncthreads();
    for (int off = 1; off < NTILES; off <<= 1) {
        int a = (t >= off) ? s[t - off] : 0;
        __syncthreads();
        s[t] += a;
        __syncthreads();
    }
    d_tileOff[t] = s[t] - v;
    __syncthreads();
    if (t < BB) {
        int off_b = d_tileOff[t * TPB];
        int nxt   = (t == BB - 1) ? s[NTILES - 1] : d_tileOff[(t + 1) * TPB];
        d_offset[t] = off_b;
        d_valid[t]  = nxt - off_b;
    }
}

// ---------------------------------------------------------------------------
// K5: order-preserving compaction. grid = NTILES x 256, one word per thread.
// ---------------------------------------------------------------------------
__global__ void k_compact(const int* __restrict__ perm,
                          const float* __restrict__ depth) {
    int blk  = blockIdx.x;
    int t    = threadIdx.x;
    int lane = t & 31, wid = t >> 5;

    int b       = blk / TPB;
    int wbatch0 = (blk - b * TPB) * TILE_W;       // word-in-batch of tile start
    int bn      = b * NN;

    unsigned bits = 0;
    if (t < TILE_W) bits = d_permbits[b * WPB + wbatch0 + t];
    int c = __popc(bits);

    // block exclusive scan (8 warps)
    int inc = c;
#pragma unroll
    for (int off = 1; off < 32; off <<= 1) {
        int n = __shfl_up_sync(0xffffffffu, inc, off);
        if (lane >= off) inc += n;
    }
    __shared__ int ws[8];
    if (lane == 31) ws[wid] = inc;
    __syncthreads();
    int wbase = 0;
#pragma unroll
    for (int w = 0; w < 8; w++) if (w < wid) wbase += ws[w];

    int slot = d_tileOff[blk] + wbase + inc - c;

    if (bits) {
        int jbase = (wbatch0 + t) * 32;           // permuted index base
        while (bits) {
            int l = __ffs(bits) - 1;
            bits &= bits - 1;
            int pix = __ldg(perm + jbase + l);
            int val = bn + pix;
            float dv = __ldg(depth + val);
            d_cd[slot] = make_int2(val, __float_as_int(dv));
            slot++;
        }
    }
}

// ---------------------------------------------------------------------------
// K6: sample + back-project; write [B,3,P] points then [B] indicator.
// ---------------------------------------------------------------------------
__global__ void k_output(const float* __restrict__ invK,
                         const float* __restrict__ bind,
                         float* __restrict__ out) {
    int i = blockIdx.x * blockDim.x + threadIdx.x;
    if (i < BB)
        out[3 * BB * PP + i] = (d_valid[i] > 0) ? 1.0f : 0.0f;
    if (i >= BB * PP) return;

    int b = i / PP;
    int p = i - b * PP;
    int vn = d_valid[b];

    int idx = 0;
    if (vn > 0)
        idx = (int)fmodf(bind[i], (float)vn) + d_offset[b];

    int2  cd  = d_cd[idx];
    int   pos = cd.x;
    float d   = __int_as_float(cd.y);
    int bb  = pos / NN;
    int pix = pos - bb * NN;
    int q   = pix / WW;
    float y = (float)q;
    float x = (float)(pix - q * WW);
    float hx = x * d, hy = y * d;

    const float* M = invK + bb * 16;
#pragma unroll
    for (int c = 0; c < 3; c++) {
        float v = fmaf(__ldg(&M[c * 4 + 0]), hx,
                  fmaf(__ldg(&M[c * 4 + 1]), hy,
                  fmaf(__ldg(&M[c * 4 + 2]), d, __ldg(&M[c * 4 + 3]))));
        out[(b * 3 + c) * PP + p] = v;
    }
}

// ---------------------------------------------------------------------------
extern "C" void kernel_launch(void* const* d_in, const int* in_sizes, int n_in,
                              void* d_out, int out_size) {
    const float* predDepth = (const float*)d_in[0];   // [B,1,H,W]
    const float* invcamK   = (const float*)d_in[1];   // [B,4,4]
    const int*   semLabel  = (const int*)  d_in[2];   // [B,1,H,W]
    const float* bind      = (const float*)d_in[3];   // [B,P]
    const int*   perm      = (const int*)  d_in[4];   // [N]
    float* out = (float*)d_out;

    k_prep   <<<NN / 256, 256>>>(perm);
    k_select <<<BN / 1024, 256>>>(semLabel, predDepth);
    k_count  <<<NTILES, 128>>>();
    k_scan   <<<1, NTILES>>>();
    k_compact<<<NTILES, 256>>>(perm, predDepth);
    k_output <<<(BB * PP) / 256, 256>>>(invcamK, bind, out);
}